// round 2
// baseline (speedup 1.0000x reference)
#include <cuda_runtime.h>

// Shapes (fixed): B=4, N=K=Q=5, L=31, D=512
// Separable conv:  y[(i,j),c,t] = As[i,c,t] + Aq[j,c,t]  (bias folded into As)
// Round 2: packed fma.rn.f32x2 in the conv (2x fp32 FMA throughput on sm_100a),
// merged coalesced weight transpose, register-tiled combine.

#define DDIM   512
#define LSEQ   31
#define NC     150
#define WHALF  1075200   // 512 * 150 * (2+3+4+5)

// Transposed weights: [half(s/q)][conv-block][(d*K + kap)*150 + c]
__device__ float g_wt[2 * WHALF];
// A tensors: [type(0=s,1=q)*100 + seq][t(31)][cf(600)]  (cf = conv*150 + c)
__device__ float g_A[200 * 31 * 600];

// ---------------- packed f32x2 helpers -------------------------------------
__device__ __forceinline__ unsigned long long pk2(float lo, float hi) {
    unsigned long long r;
    asm("mov.b64 %0, {%1, %2};" : "=l"(r) : "f"(lo), "f"(hi));
    return r;
}
__device__ __forceinline__ unsigned long long fma2(unsigned long long a,
                                                   unsigned long long b,
                                                   unsigned long long c) {
    unsigned long long d;
    asm("fma.rn.f32x2 %0, %1, %2, %3;" : "=l"(d) : "l"(a), "l"(b), "l"(c));
    return d;
}
__device__ __forceinline__ void upk2(unsigned long long v, float& lo, float& hi) {
    asm("mov.b64 {%0, %1}, %2;" : "=f"(lo), "=f"(hi) : "l"(v));
}

// ---------------------------------------------------------------------------
// Merged weight transpose, writes coalesced (c fastest).
// For conv z with kernel size K: v -> c = v%150, kap = (v/150)%K, d2 = v/(150K)
// input  w[c][cin=d2][kap]  (cin = half*512 + d)
// output g_wt[half*WHALF + woff + (d*K+kap)*150 + c]
// ---------------------------------------------------------------------------
__constant__ int c_KK[4]   = {2, 3, 4, 5};
__constant__ int c_woff[4] = {0, 153600, 384000, 691200};

__global__ void transpose_w_kernel(const float* __restrict__ w2,
                                   const float* __restrict__ w3,
                                   const float* __restrict__ w4,
                                   const float* __restrict__ w5) {
    int z  = blockIdx.z;
    int KK = c_KK[z];
    int v  = blockIdx.x * blockDim.x + threadIdx.x;
    int total = NC * 1024 * KK;
    if (v >= total) return;
    const float* w = (z == 0) ? w2 : (z == 1) ? w3 : (z == 2) ? w4 : w5;
    int c    = v % NC;
    int r    = v / NC;
    int kap  = r % KK;
    int d2   = r / KK;            // 0..1023
    int half = d2 >> 9;
    int d    = d2 & 511;
    g_wt[half * WHALF + c_woff[z] + (d * KK + kap) * NC + c] =
        w[(c * 1024 + d2) * KK + kap];
}

// ---------------------------------------------------------------------------
// Conv body with packed f32x2 FMA. Thread = out channel c, 16 t-values as
// 8 packed accumulators. xs rows: r <-> l = t0 - 2 + r (20 rows, zero padded).
// y[t] = b[c] + sum_{kap,d} w[c,d,kap] * x[t + kap - PAD, d]
// ---------------------------------------------------------------------------
template<int KK, int PAD>
__device__ __forceinline__ void conv_body(const float (*xs)[DDIM], int type, int seq,
                                          int t0, const float* __restrict__ bias,
                                          int woff, int cfoff) {
    int c = threadIdx.x;
    if (c >= NC) return;
    const float* __restrict__ wp = g_wt + type * WHALF + woff + c;
    float binit = (type == 0) ? bias[c] : 0.f;

    unsigned long long acc2[8];
#pragma unroll
    for (int t2 = 0; t2 < 8; t2++) acc2[t2] = pk2(binit, binit);

    const int ROWOFF = 2 - PAD;
    const int XN  = 16 + KK - 1;        // scalar window values, idx 0..14+KK
    const int NPE = (13 + KK) / 2 + 1;  // even-aligned pairs (2m, 2m+1)
    const int NPO = (12 + KK) / 2 + 1;  // odd-aligned pairs (2m+1, 2m+2)

    for (int d = 0; d < DDIM; d++) {
        unsigned long long w2r[KK];
#pragma unroll
        for (int k = 0; k < KK; k++) {
            float w = wp[(d * KK + k) * NC];
            w2r[k] = pk2(w, w);
        }
        float xv[XN];
#pragma unroll
        for (int j = 0; j < XN; j++)
            xv[j] = xs[j + ROWOFF][d];      // broadcast LDS
        unsigned long long pe[NPE], po[NPO];
#pragma unroll
        for (int m = 0; m < NPE; m++) pe[m] = pk2(xv[2 * m], xv[2 * m + 1]);
#pragma unroll
        for (int m = 0; m < NPO; m++) po[m] = pk2(xv[2 * m + 1], xv[2 * m + 2]);
#pragma unroll
        for (int t2 = 0; t2 < 8; t2++) {
#pragma unroll
            for (int k = 0; k < KK; k++) {
                // pair starts at j = 2*t2 + k
                unsigned long long xp = (k & 1) ? po[t2 + (k - 1) / 2]
                                                : pe[t2 + k / 2];
                acc2[t2] = fma2(w2r[k], xp, acc2[t2]);
            }
        }
    }

    float* ap = g_A + (size_t)((type * 100 + seq) * LSEQ) * 600 + cfoff + c;
#pragma unroll
    for (int t2 = 0; t2 < 8; t2++) {
        float lo, hi;
        upk2(acc2[t2], lo, hi);
        int t = t0 + 2 * t2;
        if (t < LSEQ)     ap[t * 600]       = lo;
        if (t + 1 < LSEQ) ap[(t + 1) * 600] = hi;
    }
}

__global__ __launch_bounds__(160)
void conv_all_kernel(const float* __restrict__ s, const float* __restrict__ q,
                     const float* __restrict__ b2, const float* __restrict__ b3,
                     const float* __restrict__ b4, const float* __restrict__ b5) {
    __shared__ float xs[20][DDIM];   // 40 KB window [t0-2, t0+17]
    int seqg = blockIdx.x;           // 0..199 (0..99 = s, 100..199 = q)
    int type = seqg >= 100;
    int seq  = type ? seqg - 100 : seqg;
    int t0   = blockIdx.y * 16;      // 0 or 16

    const float* __restrict__ xg = (type ? q : s) + (size_t)seq * (LSEQ * DDIM);
    for (int e = threadIdx.x; e < 20 * DDIM; e += blockDim.x) {
        int r = e >> 9;
        int d = e & 511;
        int l = t0 - 2 + r;
        xs[r][d] = (l >= 0 && l < LSEQ) ? xg[l * DDIM + d] : 0.f;
    }
    __syncthreads();

    switch (blockIdx.z) {
        case 0: conv_body<2,1>(xs, type, seq, t0, b2, 0,      0);   break;
        case 1: conv_body<3,1>(xs, type, seq, t0, b3, 153600, 150); break;
        case 2: conv_body<4,2>(xs, type, seq, t0, b4, 384000, 300); break;
        case 3: conv_body<5,2>(xs, type, seq, t0, b5, 691200, 450); break;
    }
}

// ---------------------------------------------------------------------------
// Combine: block = (b, i, jgroup-of-5). Thread = cf. As column cached in regs,
// reused across 5 q-indices -> L2 traffic 372MB -> 223MB.
//   m = max(0, max_t (As[i,t,cf] + Aq[j,t,cf]))
// ---------------------------------------------------------------------------
__global__ void combine_kernel(float* __restrict__ out) {
    int blk = blockIdx.x;            // 0..499
    int bi  = blk / 5;               // b*25 + i
    int jg  = blk - bi * 5;
    int b   = bi / 25;
    int i   = bi - b * 25;
    int cf  = threadIdx.x;           // 0..599

    const float* __restrict__ As = g_A + (size_t)bi * (LSEQ * 600) + cf;
    float as[LSEQ];
#pragma unroll
    for (int t = 0; t < LSEQ; t++) as[t] = As[t * 600];

    int conv = cf / 150;
    int c    = cf - conv * 150;

#pragma unroll
    for (int j5 = 0; j5 < 5; j5++) {
        int j = jg * 5 + j5;
        const float* __restrict__ Aq =
            g_A + (size_t)(100 + b * 25 + j) * (LSEQ * 600) + cf;
        float m = 0.f;               // relu folded into the max
#pragma unroll
        for (int t = 0; t < LSEQ; t++)
            m = fmaxf(m, as[t] + Aq[t * 600]);
        int p = (b * 25 + i) * 25 + j;
        if (c < 75)
            out[p * 300 + conv * 75 + c] = m;
        else
            out[750000 + p * 300 + conv * 75 + (c - 75)] = m;
    }
}

// ---------------------------------------------------------------------------
extern "C" void kernel_launch(void* const* d_in, const int* in_sizes, int n_in,
                              void* d_out, int out_size) {
    const float* s  = (const float*)d_in[0];
    const float* q  = (const float*)d_in[1];
    const float* w2 = (const float*)d_in[2];
    const float* b2 = (const float*)d_in[3];
    const float* w3 = (const float*)d_in[4];
    const float* b3 = (const float*)d_in[5];
    const float* w4 = (const float*)d_in[6];
    const float* b4 = (const float*)d_in[7];
    const float* w5 = (const float*)d_in[8];
    const float* b5 = (const float*)d_in[9];
    float* out = (float*)d_out;

    const int th = 256;
    int maxtot = NC * 1024 * 5;
    transpose_w_kernel<<<dim3((maxtot + th - 1) / th, 1, 4), th>>>(w2, w3, w4, w5);

    conv_all_kernel<<<dim3(200, 2, 4), 160>>>(s, q, b2, b3, b4, b5);

    combine_kernel<<<500, 600>>>(out);
}

// round 4
// speedup vs baseline: 2.4375x; 2.4375x over previous
#include <cuda_runtime.h>
#include <cuda_bf16.h>
#include <cstdint>

// ============================================================================
// CNNInteractLayer via separable conv + im2col GEMM on mma.sync (HMMA bf16).
// (tcgen05 is unusable: harness PTX target is plain sm_100, no 'a' features.)
//
// Shapes: B=4, N=K=Q=5, L=31, D=512. 200 sequences (100 s + 100 q).
// Separability: y[(i,j),c,t] = As[i,c,t] + Aq[j,c,t] + bias[c].
// One GEMM over im2col window offsets -2..+2:
//   C[6400, 640] = A[6400, 2560] @ W_type[640, 2560]^T   (both K-major)
// r = seq*32 + t (t=31 pad), k = off*512 + d, cf = conv*150 + c (600 live).
// Precision: split bf16, C = Ah*Bh + Al*Bh + Ah*Bl (fp32 accum, ~3e-5 rel).
// W is offset-sparse: per N-tile only a contiguous K range is nonzero.
// ============================================================================

#define GK     2560
#define GMROW  6400
#define GNCOL  640
#define KC     64            // K per pipeline chunk
#define TILEB  16384         // one 128row x 64k bf16 tile
#define STAGEB 65536         // Ah, Al, Bh, Bl
#define SMEM_REQ (2 * STAGEB + 1024)

__device__ __nv_bfloat16 g_Ahi[(size_t)GMROW * GK];
__device__ __nv_bfloat16 g_Alo[(size_t)GMROW * GK];
__device__ __nv_bfloat16 g_Whi[2][GNCOL][GK];
__device__ __nv_bfloat16 g_Wlo[2][GNCOL][GK];
__device__ float         g_C[(size_t)GMROW * GNCOL];
__device__ float         g_bias[GNCOL];

__constant__ int c_KKp[4] = {2, 3, 4, 5};
__constant__ int c_PAD[4] = {1, 1, 2, 2};
// live K range per N-tile (conv kernels only touch some window offsets)
__constant__ int c_k0[5] = {512, 512, 0, 0, 0};
__constant__ int c_k1[5] = {1536, 2048, 2048, 2560, 2560};

// ---------------- PTX helpers ----------------------------------------------
__device__ __forceinline__ uint32_t smem_u32(const void* p) {
    uint32_t a;
    asm("{ .reg .u64 t; cvta.to.shared.u64 t, %1; cvt.u32.u64 %0, t; }"
        : "=r"(a) : "l"(p));
    return a;
}
__device__ __forceinline__ void cpasync16(uint32_t s, const void* g) {
    asm volatile("cp.async.cg.shared.global [%0], [%1], 16;" :: "r"(s), "l"(g));
}
__device__ __forceinline__ void ldsm4(uint32_t addr, uint32_t* r) {
    asm volatile("ldmatrix.sync.aligned.m8n8.x4.shared.b16 {%0,%1,%2,%3}, [%4];"
                 : "=r"(r[0]), "=r"(r[1]), "=r"(r[2]), "=r"(r[3]) : "r"(addr));
}
__device__ __forceinline__ void ldsm2(uint32_t addr, uint32_t* r) {
    asm volatile("ldmatrix.sync.aligned.m8n8.x2.shared.b16 {%0,%1}, [%2];"
                 : "=r"(r[0]), "=r"(r[1]) : "r"(addr));
}
__device__ __forceinline__ void mma_bf16(float* c, const uint32_t* a, const uint32_t* b) {
    asm volatile("mma.sync.aligned.m16n8k16.row.col.f32.bf16.bf16.f32 "
                 "{%0,%1,%2,%3}, {%4,%5,%6,%7}, {%8,%9}, {%0,%1,%2,%3};"
                 : "+f"(c[0]), "+f"(c[1]), "+f"(c[2]), "+f"(c[3])
                 : "r"(a[0]), "r"(a[1]), "r"(a[2]), "r"(a[3]), "r"(b[0]), "r"(b[1]));
}

// ---------------------------------------------------------------------------
// Build split-bf16 W[type][cf][k] and bias. k = off*512 + d.
// ---------------------------------------------------------------------------
__global__ void build_w_kernel(const float* __restrict__ w2, const float* __restrict__ w3,
                               const float* __restrict__ w4, const float* __restrict__ w5,
                               const float* __restrict__ b2, const float* __restrict__ b3,
                               const float* __restrict__ b4, const float* __restrict__ b5) {
    int idx = blockIdx.x * blockDim.x + threadIdx.x;
    if (idx >= GNCOL * GK) return;
    int k  = idx % GK;
    int cf = idx / GK;
    int off = k >> 9, d = k & 511;
    float vs = 0.f, vq = 0.f;
    if (cf < 600) {
        int conv = cf / 150, c = cf - conv * 150;
        int KK = c_KKp[conv], PAD = c_PAD[conv];
        int kap = off - (2 - PAD);
        if (kap >= 0 && kap < KK) {
            const float* w = conv == 0 ? w2 : conv == 1 ? w3 : conv == 2 ? w4 : w5;
            vs = w[(c * 1024 + d) * KK + kap];
            vq = w[(c * 1024 + 512 + d) * KK + kap];
        }
        if (k == 0) {
            const float* bb = conv == 0 ? b2 : conv == 1 ? b3 : conv == 2 ? b4 : b5;
            g_bias[cf] = bb[c];
        }
    } else if (k == 0) {
        g_bias[cf] = 0.f;
    }
    __nv_bfloat16 hs = __float2bfloat16(vs);
    __nv_bfloat16 ls = __float2bfloat16(vs - __bfloat162float(hs));
    __nv_bfloat16 hq = __float2bfloat16(vq);
    __nv_bfloat16 lq = __float2bfloat16(vq - __bfloat162float(hq));
    g_Whi[0][cf][k] = hs;  g_Wlo[0][cf][k] = ls;
    g_Whi[1][cf][k] = hq;  g_Wlo[1][cf][k] = lq;
}

// ---------------------------------------------------------------------------
// im2col + split: A[r, k] = x[seq, t + off - 2, d] (0 if OOB or t==31).
// ---------------------------------------------------------------------------
__global__ void build_a_kernel(const float* __restrict__ s, const float* __restrict__ q) {
    int idx = blockIdx.x * blockDim.x + threadIdx.x;
    if (idx >= GMROW * (GK / 2)) return;
    int kp = idx % (GK / 2);
    int r  = idx / (GK / 2);
    int k  = kp * 2;
    int off = k >> 9, d = k & 511;
    int seq = r >> 5, t = r & 31;
    int l = t + off - 2;
    float v0 = 0.f, v1 = 0.f;
    if (t < 31 && l >= 0 && l < 31) {
        const float* x = (seq < 100 ? s : q)
                       + (size_t)(seq < 100 ? seq : seq - 100) * (31 * 512);
        float2 vv = *reinterpret_cast<const float2*>(x + l * 512 + d);
        v0 = vv.x; v1 = vv.y;
    }
    __nv_bfloat16 h0 = __float2bfloat16(v0);
    __nv_bfloat16 h1 = __float2bfloat16(v1);
    __nv_bfloat16 l0 = __float2bfloat16(v0 - __bfloat162float(h0));
    __nv_bfloat16 l1 = __float2bfloat16(v1 - __bfloat162float(h1));
    uint32_t uh = (uint32_t)__bfloat16_as_ushort(h0) | ((uint32_t)__bfloat16_as_ushort(h1) << 16);
    uint32_t ul = (uint32_t)__bfloat16_as_ushort(l0) | ((uint32_t)__bfloat16_as_ushort(l1) << 16);
    reinterpret_cast<uint32_t*>(g_Ahi)[idx] = uh;
    reinterpret_cast<uint32_t*>(g_Alo)[idx] = ul;
}

// ---------------------------------------------------------------------------
// GEMM. CTA tile 128(M)x128(N), K chunks of 64, 2-stage cp.async pipeline.
// 8 warps (4m x 2n), warp tile 32x64, mma.sync m16n8k16 bf16 (3 products).
// SW128-style swizzle: addr = row*128 + (kc ^ ((row&7)<<4)).
// ---------------------------------------------------------------------------
__device__ __forceinline__ void load_tile(uint32_t sb, const __nv_bfloat16* __restrict__ g,
                                          int k0, int tid) {
#pragma unroll
    for (int i = 0; i < 4; i++) {
        int idx = tid + i * 256;            // 0..1023
        int row = idx >> 3;
        int c16 = idx & 7;
        uint32_t sa = sb + (uint32_t)(row * 128 + ((c16 * 16) ^ ((row & 7) << 4)));
        cpasync16(sa, g + (size_t)row * GK + k0 + c16 * 8);
    }
}

__global__ __launch_bounds__(256, 1)
void gemm_kernel() {
    extern __shared__ char smem[];
    uint32_t base = (smem_u32(smem) + 1023u) & ~1023u;
    int tid = threadIdx.x, wid = tid >> 5, l = tid & 31;
    int warp_m = wid >> 1, warp_n = wid & 1;
    int nt = blockIdx.x, mt = blockIdx.y;
    int m0 = mt * 128, n0 = nt * 128;
    int type = (mt >= 25);

    int k0 = c_k0[nt];
    int nchunk = (c_k1[nt] - k0) >> 6;

    const __nv_bfloat16* gAh = g_Ahi + (size_t)m0 * GK;
    const __nv_bfloat16* gAl = g_Alo + (size_t)m0 * GK;
    const __nv_bfloat16* gBh = &g_Whi[type][n0][0];
    const __nv_bfloat16* gBl = &g_Wlo[type][n0][0];

    // per-lane ldmatrix address components (swizzle const per lane)
    uint32_t rowA   = (uint32_t)(warp_m * 32 + (l & 15));
    uint32_t abase  = rowA * 128;
    uint32_t aswz   = (rowA & 7) << 4;
    uint32_t akoff  = (uint32_t)((l >> 4) * 16);
    uint32_t rowB   = (uint32_t)(warp_n * 64 + (l & 7));
    uint32_t bbase  = rowB * 128;
    uint32_t bswz   = (rowB & 7) << 4;
    uint32_t bkoff  = (uint32_t)(((l >> 3) & 1) * 16);

    float acc[2][8][4];
#pragma unroll
    for (int mf = 0; mf < 2; mf++)
#pragma unroll
        for (int nf = 0; nf < 8; nf++)
#pragma unroll
            for (int e = 0; e < 4; e++) acc[mf][nf][e] = 0.f;

    // prologue: load chunk 0 into stage 0
    {
        uint32_t sb = base;
        load_tile(sb,             gAh, k0, tid);
        load_tile(sb + TILEB,     gAl, k0, tid);
        load_tile(sb + 2 * TILEB, gBh, k0, tid);
        load_tile(sb + 3 * TILEB, gBl, k0, tid);
        asm volatile("cp.async.commit_group;" ::: "memory");
    }

    for (int c = 0; c < nchunk; c++) {
        if (c + 1 < nchunk) {
            uint32_t sb = base + ((c + 1) & 1) * STAGEB;
            int kk = k0 + (c + 1) * KC;
            load_tile(sb,             gAh, kk, tid);
            load_tile(sb + TILEB,     gAl, kk, tid);
            load_tile(sb + 2 * TILEB, gBh, kk, tid);
            load_tile(sb + 3 * TILEB, gBl, kk, tid);
            asm volatile("cp.async.commit_group;" ::: "memory");
            asm volatile("cp.async.wait_group 1;" ::: "memory");
        } else {
            asm volatile("cp.async.wait_group 0;" ::: "memory");
        }
        __syncthreads();

        uint32_t sb = base + (c & 1) * STAGEB;
#pragma unroll
        for (int ks = 0; ks < 4; ks++) {
            uint32_t kc = (uint32_t)(ks * 32);
            uint32_t ah[2][4], al[2][4];
#pragma unroll
            for (int mf = 0; mf < 2; mf++) {
                uint32_t ao = abase + (uint32_t)(mf * 2048) + ((kc + akoff) ^ aswz);
                ldsm4(sb + ao,         ah[mf]);
                ldsm4(sb + TILEB + ao, al[mf]);
            }
#pragma unroll
            for (int nf = 0; nf < 8; nf++) {
                uint32_t bo = bbase + (uint32_t)(nf * 1024) + ((kc + bkoff) ^ bswz);
                uint32_t bh[2], bl[2];
                ldsm2(sb + 2 * TILEB + bo, bh);
                ldsm2(sb + 3 * TILEB + bo, bl);
#pragma unroll
                for (int mf = 0; mf < 2; mf++) {
                    mma_bf16(acc[mf][nf], ah[mf], bh);
                    mma_bf16(acc[mf][nf], al[mf], bh);
                    mma_bf16(acc[mf][nf], ah[mf], bl);
                }
            }
        }
        __syncthreads();
    }

    // epilogue: fp32 accum -> g_C
    int group = l >> 2, tig = l & 3;
#pragma unroll
    for (int mf = 0; mf < 2; mf++) {
#pragma unroll
        for (int nf = 0; nf < 8; nf++) {
            int row0 = m0 + warp_m * 32 + mf * 16 + group;
            int col  = n0 + warp_n * 64 + nf * 8 + tig * 2;
            float2 v0 = make_float2(acc[mf][nf][0], acc[mf][nf][1]);
            float2 v1 = make_float2(acc[mf][nf][2], acc[mf][nf][3]);
            *reinterpret_cast<float2*>(g_C + (size_t)row0 * GNCOL + col)       = v0;
            *reinterpret_cast<float2*>(g_C + (size_t)(row0 + 8) * GNCOL + col) = v1;
        }
    }
}

// ---------------------------------------------------------------------------
// Combine: m = max(0, max_t (C_s[i,t,cf] + C_q[j,t,cf] + bias[cf]))
// ---------------------------------------------------------------------------
__global__ void combine_kernel(float* __restrict__ out) {
    int blk = blockIdx.x;            // 0..499
    int bi  = blk / 5;               // b*25 + i
    int jg  = blk - bi * 5;
    int b   = bi / 25;
    int i   = bi - b * 25;
    int cf  = threadIdx.x;           // 0..599

    float bv = g_bias[cf];
    const float* __restrict__ As = g_C + (size_t)bi * (32 * GNCOL) + cf;
    float as[31];
#pragma unroll
    for (int t = 0; t < 31; t++) as[t] = As[t * GNCOL] + bv;

    int conv = cf / 150;
    int c    = cf - conv * 150;

#pragma unroll
    for (int j5 = 0; j5 < 5; j5++) {
        int j = jg * 5 + j5;
        const float* __restrict__ Aq =
            g_C + (size_t)(100 + b * 25 + j) * (32 * GNCOL) + cf;
        float m = 0.f;
#pragma unroll
        for (int t = 0; t < 31; t++)
            m = fmaxf(m, as[t] + Aq[t * GNCOL]);
        int p = (b * 25 + i) * 25 + j;
        if (c < 75)
            out[p * 300 + conv * 75 + c] = m;
        else
            out[750000 + p * 300 + conv * 75 + (c - 75)] = m;
    }
}

// ---------------------------------------------------------------------------
extern "C" void kernel_launch(void* const* d_in, const int* in_sizes, int n_in,
                              void* d_out, int out_size) {
    const float* s  = (const float*)d_in[0];
    const float* q  = (const float*)d_in[1];
    const float* w2 = (const float*)d_in[2];
    const float* b2 = (const float*)d_in[3];
    const float* w3 = (const float*)d_in[4];
    const float* b3 = (const float*)d_in[5];
    const float* w4 = (const float*)d_in[6];
    const float* b4 = (const float*)d_in[7];
    const float* w5 = (const float*)d_in[8];
    const float* b5 = (const float*)d_in[9];
    float* out = (float*)d_out;

    cudaFuncSetAttribute(gemm_kernel, cudaFuncAttributeMaxDynamicSharedMemorySize, SMEM_REQ);

    const int th = 256;
    build_w_kernel<<<(GNCOL * GK + th - 1) / th, th>>>(w2, w3, w4, w5, b2, b3, b4, b5);
    build_a_kernel<<<(GMROW * (GK / 2) + th - 1) / th, th>>>(s, q);
    gemm_kernel<<<dim3(5, 50), 256, SMEM_REQ>>>();
    combine_kernel<<<500, 600>>>(out);
}

// round 6
// speedup vs baseline: 2.4434x; 1.0024x over previous
#include <cuda_runtime.h>
#include <cuda_bf16.h>
#include <cstdint>

// ============================================================================
// CNNInteractLayer via separable conv + im2col GEMM on mma.sync (HMMA bf16).
// (tcgen05 is unusable: harness PTX target is plain sm_100, no 'a' features.)
//
// Shapes: B=4, N=K=Q=5, L=31, D=512. 200 sequences (100 s + 100 q).
// Separability: y[(i,j),c,t] = As[i,c,t] + Aq[j,c,t] + bias[c].
// One GEMM over im2col window offsets -2..+2:
//   C[6400, 640] = A[6400, 2560] @ W_type[640, 2560]^T   (both K-major)
// r = seq*32 + t (t=31 pad), k = off*512 + d, cf = conv*150 + c (600 live).
// Precision: split bf16, C = Ah*Bh + Al*Bh + Ah*Bl (fp32 accum, ~3e-5 rel).
// W is offset-sparse: per N-tile only a contiguous K range is nonzero.
// ============================================================================

#define GK     2560
#define GMROW  6400
#define GNCOL  640
#define KC     64            // K per pipeline chunk
#define TILEB  16384         // one 128row x 64k bf16 tile
#define STAGEB 65536         // Ah, Al, Bh, Bl
#define SMEM_REQ (2 * STAGEB + 1024)

__device__ __nv_bfloat16 g_Ahi[(size_t)GMROW * GK];
__device__ __nv_bfloat16 g_Alo[(size_t)GMROW * GK];
__device__ __nv_bfloat16 g_Whi[2][GNCOL][GK];
__device__ __nv_bfloat16 g_Wlo[2][GNCOL][GK];
__device__ float         g_C[(size_t)GMROW * GNCOL];
__device__ float         g_bias[GNCOL];

__constant__ int c_KKp[4] = {2, 3, 4, 5};
__constant__ int c_PAD[4] = {1, 1, 2, 2};
// live K range per N-tile (conv kernels only touch some window offsets)
__constant__ int c_k0[5] = {512, 512, 0, 0, 0};
__constant__ int c_k1[5] = {1536, 2048, 2048, 2560, 2560};

// ---------------- PTX helpers ----------------------------------------------
__device__ __forceinline__ uint32_t smem_u32(const void* p) {
    uint32_t a;
    asm("{ .reg .u64 t; cvta.to.shared.u64 t, %1; cvt.u32.u64 %0, t; }"
        : "=r"(a) : "l"(p));
    return a;
}
__device__ __forceinline__ void cpasync16(uint32_t s, const void* g) {
    asm volatile("cp.async.cg.shared.global [%0], [%1], 16;" :: "r"(s), "l"(g));
}
__device__ __forceinline__ void ldsm4(uint32_t addr, uint32_t* r) {
    asm volatile("ldmatrix.sync.aligned.m8n8.x4.shared.b16 {%0,%1,%2,%3}, [%4];"
                 : "=r"(r[0]), "=r"(r[1]), "=r"(r[2]), "=r"(r[3]) : "r"(addr));
}
__device__ __forceinline__ void ldsm2(uint32_t addr, uint32_t* r) {
    asm volatile("ldmatrix.sync.aligned.m8n8.x2.shared.b16 {%0,%1}, [%2];"
                 : "=r"(r[0]), "=r"(r[1]) : "r"(addr));
}
__device__ __forceinline__ void mma_bf16(float* c, const uint32_t* a, const uint32_t* b) {
    asm volatile("mma.sync.aligned.m16n8k16.row.col.f32.bf16.bf16.f32 "
                 "{%0,%1,%2,%3}, {%4,%5,%6,%7}, {%8,%9}, {%0,%1,%2,%3};"
                 : "+f"(c[0]), "+f"(c[1]), "+f"(c[2]), "+f"(c[3])
                 : "r"(a[0]), "r"(a[1]), "r"(a[2]), "r"(a[3]), "r"(b[0]), "r"(b[1]));
}

// ---------------------------------------------------------------------------
// Build split-bf16 W[type][cf][k] and bias. k = off*512 + d.
// ---------------------------------------------------------------------------
__global__ void build_w_kernel(const float* __restrict__ w2, const float* __restrict__ w3,
                               const float* __restrict__ w4, const float* __restrict__ w5,
                               const float* __restrict__ b2, const float* __restrict__ b3,
                               const float* __restrict__ b4, const float* __restrict__ b5) {
    int idx = blockIdx.x * blockDim.x + threadIdx.x;
    if (idx >= GNCOL * GK) return;
    int k  = idx % GK;
    int cf = idx / GK;
    int off = k >> 9, d = k & 511;
    float vs = 0.f, vq = 0.f;
    if (cf < 600) {
        int conv = cf / 150, c = cf - conv * 150;
        int KK = c_KKp[conv], PAD = c_PAD[conv];
        int kap = off - (2 - PAD);
        if (kap >= 0 && kap < KK) {
            const float* w = conv == 0 ? w2 : conv == 1 ? w3 : conv == 2 ? w4 : w5;
            vs = w[(c * 1024 + d) * KK + kap];
            vq = w[(c * 1024 + 512 + d) * KK + kap];
        }
        if (k == 0) {
            const float* bb = conv == 0 ? b2 : conv == 1 ? b3 : conv == 2 ? b4 : b5;
            g_bias[cf] = bb[c];
        }
    } else if (k == 0) {
        g_bias[cf] = 0.f;
    }
    __nv_bfloat16 hs = __float2bfloat16(vs);
    __nv_bfloat16 ls = __float2bfloat16(vs - __bfloat162float(hs));
    __nv_bfloat16 hq = __float2bfloat16(vq);
    __nv_bfloat16 lq = __float2bfloat16(vq - __bfloat162float(hq));
    g_Whi[0][cf][k] = hs;  g_Wlo[0][cf][k] = ls;
    g_Whi[1][cf][k] = hq;  g_Wlo[1][cf][k] = lq;
}

// ---------------------------------------------------------------------------
// im2col + split: A[r, k] = x[seq, t + off - 2, d] (0 if OOB or t==31).
// ---------------------------------------------------------------------------
__global__ void build_a_kernel(const float* __restrict__ s, const float* __restrict__ q) {
    int idx = blockIdx.x * blockDim.x + threadIdx.x;
    if (idx >= GMROW * (GK / 2)) return;
    int kp = idx % (GK / 2);
    int r  = idx / (GK / 2);
    int k  = kp * 2;
    int off = k >> 9, d = k & 511;
    int seq = r >> 5, t = r & 31;
    int l = t + off - 2;
    float v0 = 0.f, v1 = 0.f;
    if (t < 31 && l >= 0 && l < 31) {
        const float* x = (seq < 100 ? s : q)
                       + (size_t)(seq < 100 ? seq : seq - 100) * (31 * 512);
        float2 vv = *reinterpret_cast<const float2*>(x + l * 512 + d);
        v0 = vv.x; v1 = vv.y;
    }
    __nv_bfloat16 h0 = __float2bfloat16(v0);
    __nv_bfloat16 h1 = __float2bfloat16(v1);
    __nv_bfloat16 l0 = __float2bfloat16(v0 - __bfloat162float(h0));
    __nv_bfloat16 l1 = __float2bfloat16(v1 - __bfloat162float(h1));
    uint32_t uh = (uint32_t)__bfloat16_as_ushort(h0) | ((uint32_t)__bfloat16_as_ushort(h1) << 16);
    uint32_t ul = (uint32_t)__bfloat16_as_ushort(l0) | ((uint32_t)__bfloat16_as_ushort(l1) << 16);
    reinterpret_cast<uint32_t*>(g_Ahi)[idx] = uh;
    reinterpret_cast<uint32_t*>(g_Alo)[idx] = ul;
}

// ---------------------------------------------------------------------------
// GEMM. CTA tile 128(M)x128(N), K chunks of 64, 2-stage cp.async pipeline.
// 8 warps (4m x 2n), warp tile 32x64, mma.sync m16n8k16 bf16 (3 products).
// SW128-style swizzle: addr = row*128 + (kc ^ ((row&7)<<4)).
// ---------------------------------------------------------------------------
__device__ __forceinline__ void load_tile(uint32_t sb, const __nv_bfloat16* __restrict__ g,
                                          int k0, int tid) {
#pragma unroll
    for (int i = 0; i < 4; i++) {
        int idx = tid + i * 256;            // 0..1023
        int row = idx >> 3;
        int c16 = idx & 7;
        uint32_t sa = sb + (uint32_t)(row * 128 + ((c16 * 16) ^ ((row & 7) << 4)));
        cpasync16(sa, g + (size_t)row * GK + k0 + c16 * 8);
    }
}

__global__ __launch_bounds__(256, 1)
void gemm_kernel() {
    extern __shared__ char smem[];
    uint32_t base = (smem_u32(smem) + 1023u) & ~1023u;
    int tid = threadIdx.x, wid = tid >> 5, l = tid & 31;
    int warp_m = wid >> 1, warp_n = wid & 1;
    int nt = blockIdx.x, mt = blockIdx.y;
    int m0 = mt * 128, n0 = nt * 128;
    int type = (mt >= 25);

    int k0 = c_k0[nt];
    int nchunk = (c_k1[nt] - k0) >> 6;

    const __nv_bfloat16* gAh = g_Ahi + (size_t)m0 * GK;
    const __nv_bfloat16* gAl = g_Alo + (size_t)m0 * GK;
    const __nv_bfloat16* gBh = &g_Whi[type][n0][0];
    const __nv_bfloat16* gBl = &g_Wlo[type][n0][0];

    // per-lane ldmatrix address components (swizzle const per lane)
    uint32_t rowA   = (uint32_t)(warp_m * 32 + (l & 15));
    uint32_t abase  = rowA * 128;
    uint32_t aswz   = (rowA & 7) << 4;
    uint32_t akoff  = (uint32_t)((l >> 4) * 16);
    uint32_t rowB   = (uint32_t)(warp_n * 64 + (l & 7));
    uint32_t bbase  = rowB * 128;
    uint32_t bswz   = (rowB & 7) << 4;
    uint32_t bkoff  = (uint32_t)(((l >> 3) & 1) * 16);

    float acc[2][8][4];
#pragma unroll
    for (int mf = 0; mf < 2; mf++)
#pragma unroll
        for (int nf = 0; nf < 8; nf++)
#pragma unroll
            for (int e = 0; e < 4; e++) acc[mf][nf][e] = 0.f;

    // prologue: load chunk 0 into stage 0
    {
        uint32_t sb = base;
        load_tile(sb,             gAh, k0, tid);
        load_tile(sb + TILEB,     gAl, k0, tid);
        load_tile(sb + 2 * TILEB, gBh, k0, tid);
        load_tile(sb + 3 * TILEB, gBl, k0, tid);
        asm volatile("cp.async.commit_group;" ::: "memory");
    }

    for (int c = 0; c < nchunk; c++) {
        if (c + 1 < nchunk) {
            uint32_t sb = base + ((c + 1) & 1) * STAGEB;
            int kk = k0 + (c + 1) * KC;
            load_tile(sb,             gAh, kk, tid);
            load_tile(sb + TILEB,     gAl, kk, tid);
            load_tile(sb + 2 * TILEB, gBh, kk, tid);
            load_tile(sb + 3 * TILEB, gBl, kk, tid);
            asm volatile("cp.async.commit_group;" ::: "memory");
            asm volatile("cp.async.wait_group 1;" ::: "memory");
        } else {
            asm volatile("cp.async.wait_group 0;" ::: "memory");
        }
        __syncthreads();

        uint32_t sb = base + (c & 1) * STAGEB;
#pragma unroll
        for (int ks = 0; ks < 4; ks++) {
            uint32_t kc = (uint32_t)(ks * 32);
            uint32_t ah[2][4], al[2][4];
#pragma unroll
            for (int mf = 0; mf < 2; mf++) {
                uint32_t ao = abase + (uint32_t)(mf * 2048) + ((kc + akoff) ^ aswz);
                ldsm4(sb + ao,         ah[mf]);
                ldsm4(sb + TILEB + ao, al[mf]);
            }
#pragma unroll
            for (int nf = 0; nf < 8; nf++) {
                uint32_t bo = bbase + (uint32_t)(nf * 1024) + ((kc + bkoff) ^ bswz);
                uint32_t bh[2], bl[2];
                ldsm2(sb + 2 * TILEB + bo, bh);
                ldsm2(sb + 3 * TILEB + bo, bl);
#pragma unroll
                for (int mf = 0; mf < 2; mf++) {
                    mma_bf16(acc[mf][nf], ah[mf], bh);
                    mma_bf16(acc[mf][nf], al[mf], bh);
                    mma_bf16(acc[mf][nf], ah[mf], bl);
                }
            }
        }
        __syncthreads();
    }

    // epilogue: fp32 accum -> g_C
    int group = l >> 2, tig = l & 3;
#pragma unroll
    for (int mf = 0; mf < 2; mf++) {
#pragma unroll
        for (int nf = 0; nf < 8; nf++) {
            int row0 = m0 + warp_m * 32 + mf * 16 + group;
            int col  = n0 + warp_n * 64 + nf * 8 + tig * 2;
            float2 v0 = make_float2(acc[mf][nf][0], acc[mf][nf][1]);
            float2 v1 = make_float2(acc[mf][nf][2], acc[mf][nf][3]);
            *reinterpret_cast<float2*>(g_C + (size_t)row0 * GNCOL + col)       = v0;
            *reinterpret_cast<float2*>(g_C + (size_t)(row0 + 8) * GNCOL + col) = v1;
        }
    }
}

// ---------------------------------------------------------------------------
// Combine: m = max(0, max_t (C_s[i,t,cf] + C_q[j,t,cf] + bias[cf]))
// ---------------------------------------------------------------------------
__global__ void combine_kernel(float* __restrict__ out) {
    int blk = blockIdx.x;            // 0..499
    int bi  = blk / 5;               // b*25 + i
    int jg  = blk - bi * 5;
    int b   = bi / 25;
    int i   = bi - b * 25;
    int cf  = threadIdx.x;           // 0..599

    float bv = g_bias[cf];
    const float* __restrict__ As = g_C + (size_t)bi * (32 * GNCOL) + cf;
    float as[31];
#pragma unroll
    for (int t = 0; t < 31; t++) as[t] = As[t * GNCOL] + bv;

    int conv = cf / 150;
    int c    = cf - conv * 150;

#pragma unroll
    for (int j5 = 0; j5 < 5; j5++) {
        int j = jg * 5 + j5;
        const float* __restrict__ Aq =
            g_C + (size_t)(100 + b * 25 + j) * (32 * GNCOL) + cf;
        float m = 0.f;
#pragma unroll
        for (int t = 0; t < 31; t++)
            m = fmaxf(m, as[t] + Aq[t * GNCOL]);
        int p = (b * 25 + i) * 25 + j;
        if (c < 75)
            out[p * 300 + conv * 75 + c] = m;
        else
            out[750000 + p * 300 + conv * 75 + (c - 75)] = m;
    }
}

// ---------------------------------------------------------------------------
extern "C" void kernel_launch(void* const* d_in, const int* in_sizes, int n_in,
                              void* d_out, int out_size) {
    const float* s  = (const float*)d_in[0];
    const float* q  = (const float*)d_in[1];
    const float* w2 = (const float*)d_in[2];
    const float* b2 = (const float*)d_in[3];
    const float* w3 = (const float*)d_in[4];
    const float* b3 = (const float*)d_in[5];
    const float* w4 = (const float*)d_in[6];
    const float* b4 = (const float*)d_in[7];
    const float* w5 = (const float*)d_in[8];
    const float* b5 = (const float*)d_in[9];
    float* out = (float*)d_out;

    cudaFuncSetAttribute(gemm_kernel, cudaFuncAttributeMaxDynamicSharedMemorySize, SMEM_REQ);

    const int th = 256;
    build_w_kernel<<<(GNCOL * GK + th - 1) / th, th>>>(w2, w3, w4, w5, b2, b3, b4, b5);
    build_a_kernel<<<(GMROW * (GK / 2) + th - 1) / th, th>>>(s, q);
    gemm_kernel<<<dim3(5, 50), 256, SMEM_REQ>>>();
    combine_kernel<<<500, 600>>>(out);
}